// round 1
// baseline (speedup 1.0000x reference)
#include <cuda_runtime.h>
#include <cstdint>

// ---------------------------------------------------------------------------
// CorrelationHead: corr(P=16, DIL=2, H=7, C=256) -> FC(12544->1024) ReLU
//                  -> FC(1024->1024) ReLU -> FC(1024->4)
//
// Key structural fact: displacement dh = 2*ph - 14 needs 0 <= i+dh < 7.
// Valid (ph,i) pairs: 25 (same for (pw,j)) => only 625 of the 12544
// correlation features are ever nonzero, for every RoI. We compute a
// compacted corr [B,640] (padded) and gather the matching 625 columns of W1.
// ---------------------------------------------------------------------------

#define NB   1024      // RoIs
#define KC   640       // padded compact feature count
#define KCV  625       // valid compact features (25*25)
#define REP  1024

// valid (ph, i) pairs in lexicographic (ph, i) order; 25 entries
__device__ const int d_PH[25] = {4, 5,5,5, 6,6,6,6,6, 7,7,7,7,7,7,7,
                                 8,8,8,8,8, 9,9,9, 10};
__device__ const int d_I [25] = {6, 4,5,6, 2,3,4,5,6, 0,1,2,3,4,5,6,
                                 0,1,2,3,4, 0,1,2, 0};

// scratch (static device globals; no allocation allowed)
__device__ float g_corrc[NB * KC];     // 2.56 MB  compacted correlation
__device__ float g_W1c  [REP * KC];    // 2.56 MB  gathered W1 columns
__device__ float g_out1 [NB * REP];    // 4 MB
__device__ float g_out2 [NB * REP];    // 4 MB

// ---------------------------------------------------------------------------
// Kernel 1: gather live W1 columns (and zero the padding)
// ---------------------------------------------------------------------------
__global__ void gather_w1_kernel(const float* __restrict__ W1)
{
    int idx = blockIdx.x * 256 + threadIdx.x;
    if (idx >= REP * KC) return;
    int n = idx / KC;
    int v = idx - n * KC;
    float val = 0.f;
    if (v < KCV) {
        int vm = v / 25, vn = v - vm * 25;
        int col = (d_PH[vm] * 16 + d_PH[vn]) * 49 + d_I[vm] * 7 + d_I[vn];
        val = W1[n * 12544 + col];
    }
    g_W1c[idx] = val;
}

// ---------------------------------------------------------------------------
// Kernel 2: compacted correlation. One CTA per RoI.
// Patches staged in smem transposed to (i*7+j)-major so the channel dot
// product is contiguous (float4 LDS).
// ---------------------------------------------------------------------------
#define SSTR 260   // floats per (i,j) row in smem; 260*4 bytes, 16B aligned

extern "C" __global__ void __launch_bounds__(256)
corr_kernel(const float* __restrict__ p1, const float* __restrict__ p2)
{
    extern __shared__ float smem[];
    float* s1 = smem;
    float* s2 = smem + 49 * SSTR;

    const int b   = blockIdx.x;
    const int tid = threadIdx.x;
    const float* g1 = p1 + (size_t)b * 12544;
    const float* g2 = p2 + (size_t)b * 12544;

    // load + transpose: global [c][hw] -> smem [hw][c]
    for (int l = tid; l < 12544; l += 256) {
        int c  = l / 49;
        int hw = l - c * 49;
        s1[hw * SSTR + c] = g1[l];
        s2[hw * SSTR + c] = g2[l];
    }
    __syncthreads();

    for (int v = tid; v < KC; v += 256) {
        float out = 0.f;
        if (v < KCV) {
            int vm = v / 25, vn = v - vm * 25;
            int i = d_I[vm], j = d_I[vn];
            int r1 = i * 7 + j;
            int r2 = (i + 2 * d_PH[vm] - 14) * 7 + (j + 2 * d_PH[vn] - 14);
            const float4* a4 = (const float4*)(s1 + r1 * SSTR);
            const float4* b4 = (const float4*)(s2 + r2 * SSTR);
            float ax = 0.f, ay = 0.f, az = 0.f, aw = 0.f;
#pragma unroll 8
            for (int c4 = 0; c4 < 64; ++c4) {
                float4 x = a4[c4];
                float4 y = b4[c4];
                ax += x.x * y.x; ay += x.y * y.y;
                az += x.z * y.z; aw += x.w * y.w;
            }
            out = (ax + ay) + (az + aw);
        }
        g_corrc[b * KC + v] = out;
    }
}

// ---------------------------------------------------------------------------
// Kernel 3/4: tf32 mma.sync GEMM   C[M,N] = A[M,K] @ B[N,K]^T + bias, (ReLU)
// M = N = 1024 fixed. BM=BN=64, BK=32, 256 threads (8 warps, 2x4),
// per-warp 32x16 via 2x2 m16n8k8 tiles. fp32 accumulate; operands rounded
// to tf32 with cvt.rna at the smem-fill stage (unbiased rounding).
// MODE 0: A=g_corrc, B=g_W1c, C=g_out1.   MODE 1: A=g_out1, B=arg, C=g_out2.
// ---------------------------------------------------------------------------
__device__ __forceinline__ unsigned f2tf(float x)
{
    unsigned u;
    asm("cvt.rna.tf32.f32 %0, %1;" : "=r"(u) : "f"(x));
    return u;
}

__device__ __forceinline__ void mma8(float* c, const unsigned* a, const unsigned* b)
{
    asm volatile(
        "mma.sync.aligned.m16n8k8.row.col.f32.tf32.tf32.f32 "
        "{%0,%1,%2,%3}, {%4,%5,%6,%7}, {%8,%9}, {%0,%1,%2,%3};\n"
        : "+f"(c[0]), "+f"(c[1]), "+f"(c[2]), "+f"(c[3])
        : "r"(a[0]), "r"(a[1]), "r"(a[2]), "r"(a[3]), "r"(b[0]), "r"(b[1]));
}

template <int K, bool RELU, int MODE>
__global__ void __launch_bounds__(256)
gemm_tf32_kernel(const float* __restrict__ Bext, const float* __restrict__ bias)
{
    const float* A;
    const float* Bm;
    float*       Cm;
    if (MODE == 0) { A = g_corrc; Bm = g_W1c; Cm = g_out1; }
    else           { A = g_out1;  Bm = Bext;  Cm = g_out2; }

    __shared__ unsigned As[64 * 36];
    __shared__ unsigned Bs[64 * 36];

    const int tid  = threadIdx.x;
    const int warp = tid >> 5, lane = tid & 31;
    const int wm   = warp & 1, wn = warp >> 2 == 0 ? (warp >> 1) : (warp >> 1); // wn = warp>>1
    const int wn2  = warp >> 1;
    const int grp  = lane >> 2, qd = lane & 3;

    float acc[2][2][4];
#pragma unroll
    for (int a = 0; a < 2; a++)
#pragma unroll
        for (int bb = 0; bb < 2; bb++)
#pragma unroll
            for (int t = 0; t < 4; t++) acc[a][bb][t] = 0.f;

    const int row = tid >> 3;           // 0..31
    const int q   = (tid & 7) * 4;      // 0..28
    const float* Ag = A  + (size_t)(blockIdx.y * 64 + row) * K + q;
    const float* Bg = Bm + (size_t)(blockIdx.x * 64 + row) * K + q;

    for (int kt = 0; kt < K; kt += 32) {
        float4 av0 = *(const float4*)(Ag + kt);
        float4 av1 = *(const float4*)(Ag + (size_t)32 * K + kt);
        float4 bv0 = *(const float4*)(Bg + kt);
        float4 bv1 = *(const float4*)(Bg + (size_t)32 * K + kt);

        __syncthreads();   // previous tile fully consumed
        {
            uint4 u;
            u.x = f2tf(av0.x); u.y = f2tf(av0.y); u.z = f2tf(av0.z); u.w = f2tf(av0.w);
            *(uint4*)&As[row * 36 + q] = u;
            u.x = f2tf(av1.x); u.y = f2tf(av1.y); u.z = f2tf(av1.z); u.w = f2tf(av1.w);
            *(uint4*)&As[(row + 32) * 36 + q] = u;
            u.x = f2tf(bv0.x); u.y = f2tf(bv0.y); u.z = f2tf(bv0.z); u.w = f2tf(bv0.w);
            *(uint4*)&Bs[row * 36 + q] = u;
            u.x = f2tf(bv1.x); u.y = f2tf(bv1.y); u.z = f2tf(bv1.z); u.w = f2tf(bv1.w);
            *(uint4*)&Bs[(row + 32) * 36 + q] = u;
        }
        __syncthreads();

#pragma unroll
        for (int k8 = 0; k8 < 32; k8 += 8) {
            unsigned af[2][4], bf[2][2];
#pragma unroll
            for (int mt = 0; mt < 2; mt++) {
                int r0 = wm * 32 + mt * 16 + grp;
                af[mt][0] = As[r0 * 36 + k8 + qd];
                af[mt][1] = As[(r0 + 8) * 36 + k8 + qd];
                af[mt][2] = As[r0 * 36 + k8 + qd + 4];
                af[mt][3] = As[(r0 + 8) * 36 + k8 + qd + 4];
            }
#pragma unroll
            for (int nt = 0; nt < 2; nt++) {
                int c0 = wn2 * 16 + nt * 8 + grp;
                bf[nt][0] = Bs[c0 * 36 + k8 + qd];
                bf[nt][1] = Bs[c0 * 36 + k8 + qd + 4];
            }
#pragma unroll
            for (int mt = 0; mt < 2; mt++)
#pragma unroll
                for (int nt = 0; nt < 2; nt++)
                    mma8(acc[mt][nt], af[mt], bf[nt]);
        }
    }

    // epilogue: bias (+ReLU), scalar stores
#pragma unroll
    for (int mt = 0; mt < 2; mt++) {
#pragma unroll
        for (int nt = 0; nt < 2; nt++) {
            int rg = blockIdx.y * 64 + wm * 32 + mt * 16 + grp;
            int cg = blockIdx.x * 64 + wn2 * 16 + nt * 8 + qd * 2;
#pragma unroll
            for (int t = 0; t < 4; t++) {
                int r = rg + (t >> 1) * 8;
                int c = cg + (t & 1);
                float v = acc[mt][nt][t] + __ldg(&bias[c]);
                if (RELU) v = fmaxf(v, 0.f);
                Cm[(size_t)r * 1024 + c] = v;
            }
        }
    }
}

// ---------------------------------------------------------------------------
// Kernel 5: FC3  out[b, o<4] = g_out2[b,:] . W3[o,:] + b3[o]
// ---------------------------------------------------------------------------
__global__ void __launch_bounds__(128)
fc3_kernel(const float* __restrict__ W3, const float* __restrict__ b3,
           float* __restrict__ out)
{
    int b    = blockIdx.x;
    int warp = threadIdx.x >> 5;    // output index 0..3
    int lane = threadIdx.x & 31;
    const float* x = g_out2 + (size_t)b * 1024;
    const float* w = W3 + warp * 1024;
    float acc = 0.f;
#pragma unroll 8
    for (int k = lane; k < 1024; k += 32) acc += x[k] * w[k];
#pragma unroll
    for (int off = 16; off; off >>= 1)
        acc += __shfl_xor_sync(0xffffffffu, acc, off);
    if (lane == 0) out[b * 4 + warp] = acc + b3[warp];
}

// ---------------------------------------------------------------------------
// launch
// ---------------------------------------------------------------------------
extern "C" void kernel_launch(void* const* d_in, const int* in_sizes, int n_in,
                              void* d_out, int out_size)
{
    const float* p1 = (const float*)d_in[0];
    const float* p2 = (const float*)d_in[1];
    const float* W1 = (const float*)d_in[2];
    const float* b1 = (const float*)d_in[3];
    const float* W2 = (const float*)d_in[4];
    const float* b2 = (const float*)d_in[5];
    const float* W3 = (const float*)d_in[6];
    const float* b3 = (const float*)d_in[7];
    float* out = (float*)d_out;
    (void)in_sizes; (void)n_in; (void)out_size;

    const int corr_smem = 2 * 49 * SSTR * (int)sizeof(float);  // 101,920 B
    cudaFuncSetAttribute(corr_kernel,
                         cudaFuncAttributeMaxDynamicSharedMemorySize, corr_smem);

    gather_w1_kernel<<<(REP * KC + 255) / 256, 256>>>(W1);
    corr_kernel<<<NB, 256, corr_smem>>>(p1, p2);
    gemm_tf32_kernel<KC,   true, 0><<<dim3(16, 16), 256>>>(nullptr, b1);
    gemm_tf32_kernel<1024, true, 1><<<dim3(16, 16), 256>>>(W2, b2);
    fc3_kernel<<<NB, 128>>>(W3, b3, out);
}

// round 2
// speedup vs baseline: 1.0128x; 1.0128x over previous
#include <cuda_runtime.h>
#include <cstdint>

// ---------------------------------------------------------------------------
// CorrelationHead: corr(P=16, DIL=2, H=7, C=256) -> FC(12544->1024) ReLU
//                  -> FC(1024->1024) ReLU -> FC(1024->4)
//
// Structural sparsity: only 625 of 12544 correlation features can be nonzero.
// They are exactly the Gram entries <x1[i,j,:], x2[i',j',:]> with i==i' (mod 2)
// and j==j' (mod 2): 4 parity classes of sizes 16/12/12/9 -> 16^2+12^2+12^2+9^2
// = 625. We compute those Gram blocks directly (warp 4x4 tiles over pairs,
// lanes split channels), gather the matching 625 columns of W1, and run two
// tf32 mma GEMMs (cp.async double-buffered) + a tiny FC3.
// All tf32 rounding (cvt.rna) happens at the producers, so GEMM hot loops are
// pure LDS + MMA.
// ---------------------------------------------------------------------------

#define NB   1024
#define KC   640       // padded compact feature count
#define KCV  625
#define REP  1024
#define NTILES 43      // 16 + 9 + 9 + 9 warp tiles (4x4 pair tiles)

// scratch (static device globals; zero-initialized; no allocation allowed)
__device__ float g_corrc[NB * KC];     // compacted correlation (tf32-rounded)
__device__ float g_W1c  [REP * KC];    // gathered W1 columns (tf32-rounded)
__device__ float g_W2r  [REP * REP];   // W2 tf32-rounded
__device__ float g_out1 [NB * REP];    // FC1 out (tf32-rounded)
__device__ float g_out2 [NB * REP];    // FC2 out (fp32)

// correlation tile tables (built by init kernel; deterministic)
__device__ int g_tileA[NTILES * 4];    // x1 position rows (0..48)
__device__ int g_tileB[NTILES * 4];    // x2 position rows
__device__ int g_tileU[NTILES * 16];   // compact output index u, or -1

// ---------------------------------------------------------------------------
// helpers
// ---------------------------------------------------------------------------
__device__ __forceinline__ float tf32r(float x)
{
    unsigned u;
    asm("cvt.rna.tf32.f32 %0, %1;" : "=r"(u) : "f"(x));
    return __uint_as_float(u);
}

__device__ __forceinline__ void class_meta(int c, int& ni, int& nj, int& off)
{
    ni  = (c >> 1) ? 3 : 4;                 // i-parity: even -> {0,2,4,6}
    nj  = (c & 1)  ? 3 : 4;                 // j-parity
    off = (c == 0) ? 0 : (c == 1) ? 256 : (c == 2) ? 400 : 544;
}

__device__ __forceinline__ int local_pos(int c, int l)
{
    int pi = c >> 1, pj = c & 1;
    int nj = pj ? 3 : 4;
    int i  = 2 * (l / nj) + pi;
    int j  = 2 * (l % nj) + pj;
    return i * 7 + j;
}

// ---------------------------------------------------------------------------
// Kernel 0: build correlation tile tables
// ---------------------------------------------------------------------------
__global__ void init_tables_kernel()
{
    int t = threadIdx.x;
    if (t >= NTILES) return;
    int c, tl;
    if      (t < 16) { c = 0; tl = t; }
    else if (t < 25) { c = 1; tl = t - 16; }
    else if (t < 34) { c = 2; tl = t - 25; }
    else             { c = 3; tl = t - 34; }
    int ni, nj, off;
    class_meta(c, ni, nj, off);
    int nc = ni * nj;
    int ts = (c == 0) ? 4 : 3;              // tiles per side
    int a0 = (tl / ts) * 4, b0 = (tl % ts) * 4;
#pragma unroll
    for (int k = 0; k < 4; k++) {
        int al = a0 + k, bl = b0 + k;
        g_tileA[t * 4 + k] = (al < nc) ? local_pos(c, al) : 0;
        g_tileB[t * 4 + k] = (bl < nc) ? local_pos(c, bl) : 0;
    }
#pragma unroll
    for (int li = 0; li < 16; li++) {
        int al = a0 + (li >> 2), bl = b0 + (li & 3);
        g_tileU[t * 16 + li] = (al < nc && bl < nc) ? (off + al * nc + bl) : -1;
    }
}

// ---------------------------------------------------------------------------
// Kernel 1: gather live W1 columns (class-major u ordering), tf32-round
// ---------------------------------------------------------------------------
__global__ void gather_w1_kernel(const float* __restrict__ W1)
{
    int idx = blockIdx.x * 256 + threadIdx.x;
    if (idx >= REP * KC) return;
    int n = idx / KC;
    int u = idx - n * KC;
    float val = 0.f;
    if (u < KCV) {
        int c, rem;
        if      (u < 256) { c = 0; rem = u; }
        else if (u < 400) { c = 1; rem = u - 256; }
        else if (u < 544) { c = 2; rem = u - 400; }
        else              { c = 3; rem = u - 544; }
        int ni, nj, off;
        class_meta(c, ni, nj, off);
        int nc = ni * nj;
        int al = rem / nc, bl = rem - al * nc;
        int pi = c >> 1, pj = c & 1;
        int i  = 2 * (al / nj) + pi, j  = 2 * (al % nj) + pj;
        int i2 = 2 * (bl / nj) + pi, j2 = 2 * (bl % nj) + pj;
        int ph = ((i2 - i) + 14) >> 1;
        int pw = ((j2 - j) + 14) >> 1;
        int col = (ph * 16 + pw) * 49 + i * 7 + j;
        val = tf32r(W1[n * 12544 + col]);
    }
    g_W1c[idx] = val;
}

// ---------------------------------------------------------------------------
// Kernel 2: W2 tf32 pre-round
// ---------------------------------------------------------------------------
__global__ void round_w2_kernel(const float* __restrict__ W2)
{
    int i = blockIdx.x * 256 + threadIdx.x;
    if (i < REP * REP) g_W2r[i] = tf32r(W2[i]);
}

// ---------------------------------------------------------------------------
// Kernel 3: correlation via parity-class Gram tiles. One CTA per RoI.
// smem: x1,x2 transposed to [pos][chan] (stride 257, conflict-free), plus
// per-warp reduce scratch.
// ---------------------------------------------------------------------------
#define SSTR 257
#define CORR_SMEM (2 * 49 * SSTR * 4 + 8 * 16 * 33 * 4)   // 117,640 B

__global__ void __launch_bounds__(256)
corr_kernel(const float* __restrict__ p1, const float* __restrict__ p2)
{
    extern __shared__ float smem[];
    float* s1   = smem;
    float* s2   = smem + 49 * SSTR;
    float* sred = smem + 2 * 49 * SSTR;   // [8 warps][16 accs][33]

    const int b   = blockIdx.x;
    const int tid = threadIdx.x;
    const float* g1 = p1 + (size_t)b * 12544;
    const float* g2 = p2 + (size_t)b * 12544;

    // load + transpose: global [c][hw] -> smem [hw][c]
    for (int l = tid; l < 12544; l += 256) {
        int ch = l / 49;
        int hw = l - ch * 49;
        s1[hw * SSTR + ch] = g1[l];
        s2[hw * SSTR + ch] = g2[l];
    }
    __syncthreads();

    const int wid  = tid >> 5, lane = tid & 31;
    float* sr = sred + wid * 16 * 33;

    for (int t = wid; t < NTILES; t += 8) {
        int ra[4], rb[4];
#pragma unroll
        for (int k = 0; k < 4; k++) {
            ra[k] = __ldg(&g_tileA[t * 4 + k]) * SSTR;
            rb[k] = __ldg(&g_tileB[t * 4 + k]) * SSTR;
        }
        float acc[16];
#pragma unroll
        for (int i = 0; i < 16; i++) acc[i] = 0.f;

#pragma unroll
        for (int chh = 0; chh < 8; chh++) {
            int cc = lane + 32 * chh;
            float a0 = s1[ra[0] + cc], a1 = s1[ra[1] + cc];
            float a2 = s1[ra[2] + cc], a3 = s1[ra[3] + cc];
            float b0 = s2[rb[0] + cc], b1 = s2[rb[1] + cc];
            float b2 = s2[rb[2] + cc], b3 = s2[rb[3] + cc];
            acc[ 0] += a0 * b0; acc[ 1] += a0 * b1; acc[ 2] += a0 * b2; acc[ 3] += a0 * b3;
            acc[ 4] += a1 * b0; acc[ 5] += a1 * b1; acc[ 6] += a1 * b2; acc[ 7] += a1 * b3;
            acc[ 8] += a2 * b0; acc[ 9] += a2 * b1; acc[10] += a2 * b2; acc[11] += a2 * b3;
            acc[12] += a3 * b0; acc[13] += a3 * b1; acc[14] += a3 * b2; acc[15] += a3 * b3;
        }
#pragma unroll
        for (int i = 0; i < 16; i++) sr[i * 33 + lane] = acc[i];
        __syncwarp();
        if (lane < 16) {
            float s = 0.f;
#pragma unroll
            for (int q = 0; q < 32; q++) s += sr[lane * 33 + q];
            int u = g_tileU[t * 16 + lane];
            if (u >= 0) g_corrc[b * KC + u] = tf32r(s);
        }
        __syncwarp();   // protect sred before next tile's stores
    }
    // pad entries u in [625,640) stay zero (zero-initialized global, never written)
}

// ---------------------------------------------------------------------------
// Kernel 4/5: tf32 GEMM  C[M=1024, N=1024] = A[1024,K] @ B[1024,K]^T + bias
// BM=BN=64, BK=32, 128 threads (4 warps, warp tile 32x32 = 2x4 m16n8k8),
// cp.async double-buffered, operands pre-rounded to tf32 by producers.
// MODE 0: A=g_corrc, B=g_W1c, C=g_out1 (tf32-rounded). MODE 1: A=g_out1,
// B=g_W2r, C=g_out2 (fp32).
// ---------------------------------------------------------------------------
__device__ __forceinline__ void cpa16(float* s, const float* g)
{
    unsigned sa = (unsigned)__cvta_generic_to_shared(s);
    asm volatile("cp.async.cg.shared.global [%0], [%1], 16;" :: "r"(sa), "l"(g));
}

__device__ __forceinline__ void mma8(float* c, const unsigned* a, const unsigned* b)
{
    asm volatile(
        "mma.sync.aligned.m16n8k8.row.col.f32.tf32.tf32.f32 "
        "{%0,%1,%2,%3}, {%4,%5,%6,%7}, {%8,%9}, {%0,%1,%2,%3};\n"
        : "+f"(c[0]), "+f"(c[1]), "+f"(c[2]), "+f"(c[3])
        : "r"(a[0]), "r"(a[1]), "r"(a[2]), "r"(a[3]), "r"(b[0]), "r"(b[1]));
}

template <int K, bool RELU, int MODE>
__global__ void __launch_bounds__(128)
gemm_tf32_kernel(const float* __restrict__ bias)
{
    const float* A;
    const float* Bm;
    float*       Cm;
    if (MODE == 0) { A = g_corrc; Bm = g_W1c; Cm = g_out1; }
    else           { A = g_out1;  Bm = g_W2r; Cm = g_out2; }

    __shared__ float As[2][64 * 36];
    __shared__ float Bs[2][64 * 36];

    const int tid  = threadIdx.x;
    const int warp = tid >> 5, lane = tid & 31;
    const int wm   = warp & 1, wn = warp >> 1;
    const int grp  = lane >> 2, qd = lane & 3;

    const int lrow = tid >> 3;          // 0..15
    const int lq   = (tid & 7) * 4;     // 0,4,...,28
    const float* Ag = A  + (size_t)(blockIdx.y * 64 + lrow) * K + lq;
    const float* Bg = Bm + (size_t)(blockIdx.x * 64 + lrow) * K + lq;

    float acc[2][4][4];
#pragma unroll
    for (int mt = 0; mt < 2; mt++)
#pragma unroll
        for (int nt = 0; nt < 4; nt++)
#pragma unroll
            for (int t = 0; t < 4; t++) acc[mt][nt][t] = 0.f;

    auto loadstage = [&](int buf, int kt) {
#pragma unroll
        for (int rr = 0; rr < 4; rr++) {
            cpa16(&As[buf][(lrow + 16 * rr) * 36 + lq], Ag + kt + (size_t)16 * rr * K);
            cpa16(&Bs[buf][(lrow + 16 * rr) * 36 + lq], Bg + kt + (size_t)16 * rr * K);
        }
    };

    loadstage(0, 0);
    asm volatile("cp.async.commit_group;" ::: "memory");

    const int NT = K / 32;
    for (int kt = 0; kt < NT; kt++) {
        asm volatile("cp.async.wait_group 0;" ::: "memory");
        __syncthreads();
        if (kt + 1 < NT) {
            loadstage((kt + 1) & 1, (kt + 1) * 32);
            asm volatile("cp.async.commit_group;" ::: "memory");
        }
        const float* as = As[kt & 1];
        const float* bs = Bs[kt & 1];
#pragma unroll
        for (int k8 = 0; k8 < 32; k8 += 8) {
            unsigned af[2][4], bf[4][2];
#pragma unroll
            for (int mt = 0; mt < 2; mt++) {
                int r0 = wm * 32 + mt * 16 + grp;
                af[mt][0] = __float_as_uint(as[r0 * 36 + k8 + qd]);
                af[mt][1] = __float_as_uint(as[(r0 + 8) * 36 + k8 + qd]);
                af[mt][2] = __float_as_uint(as[r0 * 36 + k8 + qd + 4]);
                af[mt][3] = __float_as_uint(as[(r0 + 8) * 36 + k8 + qd + 4]);
            }
#pragma unroll
            for (int nt = 0; nt < 4; nt++) {
                int c0 = wn * 32 + nt * 8 + grp;
                bf[nt][0] = __float_as_uint(bs[c0 * 36 + k8 + qd]);
                bf[nt][1] = __float_as_uint(bs[c0 * 36 + k8 + qd + 4]);
            }
#pragma unroll
            for (int mt = 0; mt < 2; mt++)
#pragma unroll
                for (int nt = 0; nt < 4; nt++)
                    mma8(acc[mt][nt], af[mt], bf[nt]);
        }
    }

    // epilogue
#pragma unroll
    for (int mt = 0; mt < 2; mt++) {
#pragma unroll
        for (int nt = 0; nt < 4; nt++) {
            int rg = blockIdx.y * 64 + wm * 32 + mt * 16 + grp;
            int cg = blockIdx.x * 64 + wn * 32 + nt * 8 + qd * 2;
#pragma unroll
            for (int t = 0; t < 4; t++) {
                int r = rg + (t >> 1) * 8;
                int c = cg + (t & 1);
                float v = acc[mt][nt][t] + __ldg(&bias[c]);
                if (RELU) v = fmaxf(v, 0.f);
                if (MODE == 0) v = tf32r(v);   // pre-round for FC2 consumption
                Cm[(size_t)r * 1024 + c] = v;
            }
        }
    }
}

// ---------------------------------------------------------------------------
// Kernel 6: FC3  out[b, o<4] = g_out2[b,:] . W3[o,:] + b3[o]  (fp32)
// ---------------------------------------------------------------------------
__global__ void __launch_bounds__(128)
fc3_kernel(const float* __restrict__ W3, const float* __restrict__ b3,
           float* __restrict__ out)
{
    int b    = blockIdx.x;
    int warp = threadIdx.x >> 5;
    int lane = threadIdx.x & 31;
    const float* x = g_out2 + (size_t)b * 1024;
    const float* w = W3 + warp * 1024;
    float acc = 0.f;
#pragma unroll 8
    for (int k = lane; k < 1024; k += 32) acc += x[k] * w[k];
#pragma unroll
    for (int off = 16; off; off >>= 1)
        acc += __shfl_xor_sync(0xffffffffu, acc, off);
    if (lane == 0) out[b * 4 + warp] = acc + b3[warp];
}

// ---------------------------------------------------------------------------
// launch
// ---------------------------------------------------------------------------
extern "C" void kernel_launch(void* const* d_in, const int* in_sizes, int n_in,
                              void* d_out, int out_size)
{
    const float* p1 = (const float*)d_in[0];
    const float* p2 = (const float*)d_in[1];
    const float* W1 = (const float*)d_in[2];
    const float* b1 = (const float*)d_in[3];
    const float* W2 = (const float*)d_in[4];
    const float* b2 = (const float*)d_in[5];
    const float* W3 = (const float*)d_in[6];
    const float* b3 = (const float*)d_in[7];
    float* out = (float*)d_out;
    (void)in_sizes; (void)n_in; (void)out_size;

    cudaFuncSetAttribute(corr_kernel,
                         cudaFuncAttributeMaxDynamicSharedMemorySize, CORR_SMEM);

    init_tables_kernel<<<1, 64>>>();
    gather_w1_kernel<<<(REP * KC + 255) / 256, 256>>>(W1);
    round_w2_kernel<<<(REP * REP + 255) / 256, 256>>>(W2);
    corr_kernel<<<NB, 256, CORR_SMEM>>>(p1, p2);
    gemm_tf32_kernel<KC,   true, 0><<<dim3(16, 16), 128>>>(b1);
    gemm_tf32_kernel<1024, true, 1><<<dim3(16, 16), 128>>>(b2);
    fc3_kernel<<<NB, 128>>>(W3, b3, out);
}